// round 12
// baseline (speedup 1.0000x reference)
#include <cuda_runtime.h>
#include <cuda_fp16.h>
#include <math.h>
#include <stdint.h>

#define LL 2048
#define CCdim 2048
#define BB 4
#define DD 1024
#define ZZ 128
#define EE (2*DD+ZZ)   // 2176
#define M1 (LL*BB)     // 8192
#define ZB 256         // fused q/k width (Z + 128 bias cols)

#define STAGES 4
// stage: A 256x32 halves (16KB) + B 128x32 halves (8KB) = 24KB; x4 = 96KB
#define SMEM_BYTES (STAGES*(4096+2048)*4)

// ---------------- scratch (device globals: allocation-free) ----------------
__device__ __align__(256) __half h_x[M1*DD];          // LN output (fp16)
__device__ __align__(256) float  g_u[M1*DD];          // sigmoid gate
__device__ __align__(256) float  g_r[M1*DD];          // silu gate
__device__ __align__(256) __half h_q2[M1*ZB];         // [q*scale | rot(alpha)]
__device__ __align__(256) __half h_k2[M1*ZB];         // [k       | rot(beta) ]
__device__ __align__(256) __half h_vT[(size_t)BB*DD*CCdim]; // silu(v) transposed [b][e][c]
__device__ __align__(256) float  g_h[M1*DD];          // attn @ v
__device__ __align__(256) __half h_hx[M1*DD];         // h*r (fp16)
__device__ __align__(256) float  g_qk[(size_t)BB*LL*CCdim];  // scores fp32
__device__ __align__(256) __half h_p[(size_t)BB*LL*CCdim];   // probs fp16
__device__ __align__(256) __half h_wq[EE*DD];
__device__ __align__(256) __half h_wk[ZZ*DD];
__device__ __align__(256) __half h_wv[DD*DD];
__device__ __align__(256) __half h_wh[DD*DD];
__device__ __align__(256) __half h_kin[M1*DD];
__device__ __align__(256) __half h_vin[M1*DD];

__device__ __forceinline__ float sigmoidf_(float v){ return 1.f/(1.f+expf(-v)); }
__device__ __forceinline__ float siluf_(float v){ return v/(1.f+expf(-v)); }

__device__ __forceinline__ void mma16(float c[4], const uint32_t a[4], const uint32_t b[2]){
    asm volatile("mma.sync.aligned.m16n8k16.row.col.f32.f16.f16.f32 "
        "{%0,%1,%2,%3}, {%4,%5,%6,%7}, {%8,%9}, {%0,%1,%2,%3};\n"
        : "+f"(c[0]), "+f"(c[1]), "+f"(c[2]), "+f"(c[3])
        : "r"(a[0]), "r"(a[1]), "r"(a[2]), "r"(a[3]), "r"(b[0]), "r"(b[1]));
}
__device__ __forceinline__ void cpa16(uint32_t s, const __half* g){
    asm volatile("cp.async.cg.shared.global [%0], [%1], 16;\n" :: "r"(s), "l"(g));
}
__device__ __forceinline__ void cpa_commit(){ asm volatile("cp.async.commit_group;\n"); }
template<int N>
__device__ __forceinline__ void cpa_wait(){ asm volatile("cp.async.wait_group %0;\n" :: "n"(N)); }

// ---------------- fp32 -> fp16 (8 elems/thread) ----------------
__global__ void f2h_kernel(const float* __restrict__ in, __half* __restrict__ out)
{
    long i = ((long)blockIdx.x*256 + threadIdx.x) * 8;
    float4 a = *(const float4*)(in + i);
    float4 b = *(const float4*)(in + i + 4);
    __half2 r[4];
    r[0] = __floats2half2_rn(a.x, a.y);
    r[1] = __floats2half2_rn(a.z, a.w);
    r[2] = __floats2half2_rn(b.x, b.y);
    r[3] = __floats2half2_rn(b.z, b.w);
    *(uint4*)(out + i) = *(uint4*)r;
}

// ---------------- LayerNorm -> fp16 ----------------
__global__ void ln_kernel(const float* __restrict__ q, const float* __restrict__ w,
                          const float* __restrict__ b, __half* __restrict__ x)
{
    int row = blockIdx.x;
    int tid = threadIdx.x;
    const float4* p = (const float4*)(q + (size_t)row*DD);
    float4 v = p[tid];
    float s  = v.x+v.y+v.z+v.w;
    float ss = v.x*v.x+v.y*v.y+v.z*v.z+v.w*v.w;
    #pragma unroll
    for (int o=16;o;o>>=1){ s += __shfl_xor_sync(~0u,s,o); ss += __shfl_xor_sync(~0u,ss,o); }
    __shared__ float shA[8], shB[8];
    int warp = tid>>5, lane = tid&31;
    if (lane==0){ shA[warp]=s; shB[warp]=ss; }
    __syncthreads();
    float tots=0.f, totss=0.f;
    #pragma unroll
    for (int wdx=0; wdx<8; ++wdx){ tots += shA[wdx]; totss += shB[wdx]; }
    float mean = tots*(1.f/DD);
    float var  = totss*(1.f/DD) - mean*mean;
    float rstd = rsqrtf(var + 1e-5f);
    float4 w4 = ((const float4*)w)[tid];
    float4 b4 = ((const float4*)b)[tid];
    __half2 o0 = __floats2half2_rn((v.x-mean)*rstd*w4.x + b4.x, (v.y-mean)*rstd*w4.y + b4.y);
    __half2 o1 = __floats2half2_rn((v.z-mean)*rstd*w4.z + b4.z, (v.w-mean)*rstd*w4.w + b4.w);
    __half2* op = (__half2*)(x + (size_t)row*DD);
    op[tid*2]   = o0;
    op[tid*2+1] = o1;
}

// ---------------- rotary tables -> bias columns of h_q2 / h_k2 ----------------
__global__ void rotab_kernel(const float* __restrict__ alpha, const float* __restrict__ beta)
{
    int m = blockIdx.x;        // l or c index, 0..2047
    int i = threadIdx.x;       // 0..63
    float f = expf((float)i * (-9.210340371976184f / 64.f));
    float ang = (float)m * f;
    float s, c;
    sincosf(ang, &s, &c);
    float a1 = alpha[i], a2 = alpha[i+64];
    __half ar0 = __float2half_rn(a1*c - a2*s);
    __half ar1 = __float2half_rn(a2*c + a1*s);
    float b1 = beta[i],  b2 = beta[i+64];
    __half br0 = __float2half_rn(b1*c - b2*s);
    __half br1 = __float2half_rn(b2*c + b1*s);
    #pragma unroll
    for (int b=0;b<BB;++b) {
        long row = (long)(m*BB + b) * ZB + ZZ;
        h_q2[row + i]      = ar0;
        h_q2[row + i + 64] = ar1;
        h_k2[row + i]      = br0;
        h_k2[row + i + 64] = br1;
    }
}

// ---------------- softmax (fp32 scores incl. fused bias) -> fp16 probs ----------------
__global__ void softmax_kernel()
{
    long row = blockIdx.x;
    const float* p = g_qk + row * (long)CCdim;
    __half* hp = h_p + row * (long)CCdim;
    int tid = threadIdx.x;
    float4 v0 = ((const float4*)p)[tid];
    float4 v1 = ((const float4*)p)[tid+256];
    float e0=v0.x, e1=v0.y, e2=v0.z, e3=v0.w, e4=v1.x, e5=v1.y, e6=v1.z, e7=v1.w;
    float mx = fmaxf(fmaxf(fmaxf(e0,e1),fmaxf(e2,e3)), fmaxf(fmaxf(e4,e5),fmaxf(e6,e7)));
    #pragma unroll
    for (int o=16;o;o>>=1) mx = fmaxf(mx, __shfl_xor_sync(~0u,mx,o));
    __shared__ float shm[8], shs[8];
    int warp = tid>>5, lane = tid&31;
    if (lane==0) shm[warp] = mx;
    __syncthreads();
    mx = shm[0];
    #pragma unroll
    for (int wdx=1; wdx<8; ++wdx) mx = fmaxf(mx, shm[wdx]);
    e0 = expf(e0-mx); e1 = expf(e1-mx); e2 = expf(e2-mx); e3 = expf(e3-mx);
    e4 = expf(e4-mx); e5 = expf(e5-mx); e6 = expf(e6-mx); e7 = expf(e7-mx);
    float s = e0+e1+e2+e3+e4+e5+e6+e7;
    #pragma unroll
    for (int o=16;o;o>>=1) s += __shfl_xor_sync(~0u,s,o);
    if (lane==0) shs[warp] = s;
    __syncthreads();
    s = 0.f;
    #pragma unroll
    for (int wdx=0; wdx<8; ++wdx) s += shs[wdx];
    float inv = 1.f/s;
    __half2 r0[2], r1[2];
    r0[0] = __floats2half2_rn(e0*inv, e1*inv);
    r0[1] = __floats2half2_rn(e2*inv, e3*inv);
    r1[0] = __floats2half2_rn(e4*inv, e5*inv);
    r1[1] = __floats2half2_rn(e6*inv, e7*inv);
    ((uint2*)hp)[tid]     = *(uint2*)r0;
    ((uint2*)hp)[tid+256] = *(uint2*)r1;
}

// ---------------- h*r -> fp16 ----------------
__global__ void hr_kernel()
{
    long i = ((long)blockIdx.x*256 + threadIdx.x) * 4;
    float4 h = *(const float4*)(g_h + i);
    float4 r = *(const float4*)(g_r + i);
    __half2 o[2];
    o[0] = __floats2half2_rn(h.x*r.x, h.y*r.y);
    o[1] = __floats2half2_rn(h.z*r.z, h.w*r.w);
    *(uint2*)(h_hx + i) = *(uint2*)o;
}

// ---------------- FP16 GEMM: CTA 256x128x32, warps 4x2 (64x64 each), 4-stage cp.async ----------------
// smem stage rows of 32 halves (16 uint32, 4 chunks of 16B), chunk swizzle c ^= (row>>1)&3.
// MODE 0: base proj -> g_u/g_r/h_q2.  1: fp32 store.  2: half(v+aux1[n]) (k proj -> h_k2).
// 4: gated residual out (fp32).       5: half(silu(v+aux1[m])) (transposed V proj).
template<int MODE>
__global__ void __launch_bounds__(256, 1)
gemm_h(const __half* __restrict__ A, const __half* __restrict__ Bm,
       int K, int lda, int ldb, long sAz, long sBz,
       float* __restrict__ CF, __half* __restrict__ CH, int ldc, long sCz,
       const float* __restrict__ aux1, const float* __restrict__ aux2)
{
    extern __shared__ uint32_t smem[];
    uint32_t* As = smem;                   // per stage: 4096 uint32 (256 rows x 16)
    uint32_t* Bs = smem + STAGES*4096;     // per stage: 2048 uint32 (128 rows x 16)
    uint32_t AsU = (uint32_t)__cvta_generic_to_shared(As);
    uint32_t BsU = (uint32_t)__cvta_generic_to_shared(Bs);

    const int bz = blockIdx.z;
    A  += (long)bz * sAz;
    Bm += (long)bz * sBz;

    const int m0 = blockIdx.y << 8, n0 = blockIdx.x << 7;
    const int tid = threadIdx.x, lane = tid & 31, wid = tid >> 5;
    const int wm = (wid >> 1) * 64;        // warp m base within tile
    const int wn = (wid & 1) * 64;         // warp n base within tile

    float acc[4][8][4];
    #pragma unroll
    for (int i=0;i<4;++i)
        #pragma unroll
        for (int j=0;j<8;++j)
            #pragma unroll
            for (int c=0;c<4;++c) acc[i][j][c] = 0.f;

    // A loader: rows (tid>>2)+{0,64,128,192}, chunk tid&3 (coalesced 64B lines)
    const int ar = tid >> 2, ac = tid & 3;
    const __half* ga = A + (long)(m0 + ar)*lda + ac*8;
    const long gaStep = (long)64*lda;
    const uint32_t sa = (uint32_t)(ar*16 + ((ac ^ ((ar>>1)&3))<<2)) * 4;  // swizzle invariant under +64 rows
    // B loader: rows (tid>>2)+{0,64}, chunk tid&3
    const __half* gb = Bm + (long)(n0 + ar)*ldb + ac*8;

    const int ktiles = K >> 5;

    auto load_tile = [&](int slot, int kt){
        uint32_t aB = AsU + (uint32_t)slot*4096*4;
        uint32_t bB = BsU + (uint32_t)slot*2048*4;
        const __half* ap = ga + (long)kt*32;
        cpa16(aB + sa,         ap);
        cpa16(aB + sa + 4096,  ap + gaStep);
        cpa16(aB + sa + 8192,  ap + 2*gaStep);
        cpa16(aB + sa + 12288, ap + 3*gaStep);
        const __half* bp = gb + (long)kt*32;
        cpa16(bB + sa,         bp);
        cpa16(bB + sa + 4096,  bp + (long)64*ldb);
    };

    auto comp = [&](int slot){
        const uint32_t* sA = As + slot*4096;
        const uint32_t* sB = Bs + slot*2048;
        #pragma unroll
        for (int ks=0; ks<2; ++ks) {
            uint32_t af[4][4], bf[8][2];
            #pragma unroll
            for (int mt=0; mt<4; ++mt) {
                int mr0 = wm + mt*16 + (lane>>2);
                int mr1 = mr0 + 8;
                int s0 = (mr0>>1)&3, s1 = (mr1>>1)&3;
                const uint32_t* p0 = sA + mr0*16 + (lane&3);
                const uint32_t* p1 = sA + mr1*16 + (lane&3);
                af[mt][0] = p0[((2*ks+0)^s0)<<2];
                af[mt][1] = p1[((2*ks+0)^s1)<<2];
                af[mt][2] = p0[((2*ks+1)^s0)<<2];
                af[mt][3] = p1[((2*ks+1)^s1)<<2];
            }
            #pragma unroll
            for (int nt=0; nt<8; ++nt) {
                int nr = wn + nt*8 + (lane>>2);
                int s = (nr>>1)&3;
                const uint32_t* p = sB + nr*16 + (lane&3);
                bf[nt][0] = p[((2*ks+0)^s)<<2];
                bf[nt][1] = p[((2*ks+1)^s)<<2];
            }
            #pragma unroll
            for (int mt=0; mt<4; ++mt)
                #pragma unroll
                for (int nt=0; nt<8; ++nt)
                    mma16(acc[mt][nt], af[mt], bf[nt]);
        }
    };

    #pragma unroll
    for (int s=0; s<STAGES-1; ++s) { load_tile(s, s); cpa_commit(); }

    for (int kt=0; kt<ktiles; ++kt) {
        cpa_wait<STAGES-2>();
        __syncthreads();
        int nk = kt + STAGES - 1;
        if (nk < ktiles) load_tile(nk & (STAGES-1), nk);
        cpa_commit();
        comp(kt & (STAGES-1));
    }

    // ---- epilogue ----
    #pragma unroll
    for (int mt=0; mt<4; ++mt) {
        #pragma unroll
        for (int ci2=0; ci2<2; ++ci2) {
            int m = m0 + wm + mt*16 + (lane>>2) + ci2*8;
            #pragma unroll
            for (int nt=0; nt<8; ++nt) {
                #pragma unroll
                for (int cj=0; cj<2; ++cj) {
                    int n = n0 + wn + nt*8 + ((lane&3)<<1) + cj;
                    float v = acc[mt][nt][ci2*2+cj];
                    if (MODE==0) {
                        v += aux1[n];
                        if (n < DD)            g_u[(long)m*DD + n]        = sigmoidf_(v);
                        else if (n < 2*DD)     g_r[(long)m*DD + (n-DD)]   = siluf_(v);
                        else                   h_q2[(long)m*ZB + (n-2*DD)] = __float2half_rn(v * 0.08838834764831845f);
                    } else if (MODE==1) {
                        CF[(long)m*ldc + n + (long)bz*sCz] = v;
                    } else if (MODE==2) {
                        CH[(long)m*ldc + n + (long)bz*sCz] = __float2half_rn(v + aux1[n]);
                    } else if (MODE==5) {
                        CH[(long)m*ldc + n + (long)bz*sCz] = __float2half_rn(siluf_(v + aux1[m]));
                    } else { // MODE 4
                        float t = siluf_(v + aux1[n]);
                        long idx = (long)m*DD + n;
                        float res = aux2[idx];
                        CF[idx] = res + g_u[idx]*(t - res);
                    }
                }
            }
        }
    }
}

// ---------------- launch ----------------
extern "C" void kernel_launch(void* const* d_in, const int* in_sizes, int n_in,
                              void* d_out, int out_size)
{
    const float* query   = (const float*)d_in[0];
    const float* key_seq = (const float*)d_in[1];
    const float* value   = (const float*)d_in[2];
    const float* wq      = (const float*)d_in[3];
    const float* bq      = (const float*)d_in[4];
    const float* wk      = (const float*)d_in[5];
    const float* bk      = (const float*)d_in[6];
    const float* wv      = (const float*)d_in[7];
    const float* bv      = (const float*)d_in[8];
    const float* wh      = (const float*)d_in[9];
    const float* bh      = (const float*)d_in[10];
    const float* ln_w    = (const float*)d_in[11];
    const float* ln_b    = (const float*)d_in[12];
    const float* alpha   = (const float*)d_in[13];
    const float* beta    = (const float*)d_in[14];
    float* out = (float*)d_out;

    __half *p_wq, *p_wk, *p_wv, *p_wh, *p_kin, *p_vin, *p_x, *p_q2, *p_k2, *p_vT, *p_hx, *p_p;
    float *p_h, *p_qk;
    cudaGetSymbolAddress((void**)&p_wq,  h_wq);
    cudaGetSymbolAddress((void**)&p_wk,  h_wk);
    cudaGetSymbolAddress((void**)&p_wv,  h_wv);
    cudaGetSymbolAddress((void**)&p_wh,  h_wh);
    cudaGetSymbolAddress((void**)&p_kin, h_kin);
    cudaGetSymbolAddress((void**)&p_vin, h_vin);
    cudaGetSymbolAddress((void**)&p_x,   h_x);
    cudaGetSymbolAddress((void**)&p_q2,  h_q2);
    cudaGetSymbolAddress((void**)&p_k2,  h_k2);
    cudaGetSymbolAddress((void**)&p_vT,  h_vT);
    cudaGetSymbolAddress((void**)&p_hx,  h_hx);
    cudaGetSymbolAddress((void**)&p_p,   h_p);
    cudaGetSymbolAddress((void**)&p_h,   g_h);
    cudaGetSymbolAddress((void**)&p_qk,  g_qk);

    static bool attr_done = false;
    if (!attr_done) {
        cudaFuncSetAttribute((const void*)gemm_h<0>, cudaFuncAttributeMaxDynamicSharedMemorySize, SMEM_BYTES);
        cudaFuncSetAttribute((const void*)gemm_h<1>, cudaFuncAttributeMaxDynamicSharedMemorySize, SMEM_BYTES);
        cudaFuncSetAttribute((const void*)gemm_h<2>, cudaFuncAttributeMaxDynamicSharedMemorySize, SMEM_BYTES);
        cudaFuncSetAttribute((const void*)gemm_h<4>, cudaFuncAttributeMaxDynamicSharedMemorySize, SMEM_BYTES);
        cudaFuncSetAttribute((const void*)gemm_h<5>, cudaFuncAttributeMaxDynamicSharedMemorySize, SMEM_BYTES);
        attr_done = true;
    }

    // 0. fp32 -> fp16 conversions
    f2h_kernel<<<EE*DD/2048, 256>>>(wq, p_wq);
    f2h_kernel<<<ZZ*DD/2048, 256>>>(wk, p_wk);
    f2h_kernel<<<DD*DD/2048, 256>>>(wv, p_wv);
    f2h_kernel<<<DD*DD/2048, 256>>>(wh, p_wh);
    f2h_kernel<<<M1*DD/2048, 256>>>(key_seq, p_kin);
    f2h_kernel<<<M1*DD/2048, 256>>>(value, p_vin);
    // 1. LayerNorm -> fp16
    ln_kernel<<<M1, 256>>>(query, ln_w, ln_b, p_x);
    // 2. rotary tables -> bias columns of h_q2 / h_k2
    rotab_kernel<<<LL, 64>>>(alpha, beta);
    // 3. base projection: u/r/q (8192 x 2176 x 1024); q lands in h_q2[:, :128]
    gemm_h<0><<<dim3(EE/128, M1/256, 1), 256, SMEM_BYTES>>>(
        p_x, p_wq, DD, DD, DD, 0, 0, nullptr, nullptr, 0, 0, bq, nullptr);
    // 4. k projection (8192 x 128 x 1024) -> h_k2[:, :128]
    gemm_h<2><<<dim3(1, M1/256, 1), 256, SMEM_BYTES>>>(
        p_kin, p_wk, DD, DD, DD, 0, 0, nullptr, p_k2, ZB, 0, bk, nullptr);
    // 5. V projection TRANSPOSED: vT[b][e][c] = silu(wv[e,:]·value[c,b,:] + bv[e])
    gemm_h<5><<<dim3(CCdim/128, DD/256, BB), 256, SMEM_BYTES>>>(
        p_wv, p_vin, DD, DD, BB*DD, 0, (long)DD,
        nullptr, p_vT, CCdim, (long)DD*CCdim, bv, nullptr);
    // 6. QK^T + rotary bias fused as K=256 GEMM -> fp32 scores
    gemm_h<1><<<dim3(CCdim/128, LL/256, BB), 256, SMEM_BYTES>>>(
        p_q2, p_k2, ZB, BB*ZB, BB*ZB, (long)ZB, (long)ZB,
        p_qk, nullptr, CCdim, (long)LL*CCdim, nullptr, nullptr);
    // 7. softmax -> fp16 probs
    softmax_kernel<<<BB*LL, 256>>>();
    // 8. attn @ V batched, B = vT (K-major)
    gemm_h<1><<<dim3(DD/128, LL/256, BB), 256, SMEM_BYTES>>>(
        p_p, p_vT, CCdim, CCdim, CCdim, (long)LL*CCdim, (long)DD*CCdim,
        p_h, nullptr, BB*DD, (long)DD, nullptr, nullptr);
    // 9. h*r -> fp16
    hr_kernel<<<M1*DD/1024, 256>>>();
    // 10. output projection + silu + gated residual (fp32 out)
    gemm_h<4><<<dim3(DD/128, M1/256, 1), 256, SMEM_BYTES>>>(
        p_hx, p_wh, DD, DD, DD, 0, 0, out, nullptr, DD, 0, bh, query);
}

// round 13
// speedup vs baseline: 1.3200x; 1.3200x over previous
#include <cuda_runtime.h>
#include <cuda_fp16.h>
#include <math.h>
#include <stdint.h>

#define LL 2048
#define CCdim 2048
#define BB 4
#define DD 1024
#define ZZ 128
#define EE (2*DD+ZZ)   // 2176
#define M1 (LL*BB)     // 8192
#define ZB 256         // fused q/k width (Z + 128 bias cols)

#define STAGES 4
#define SMEM_BYTES (STAGES*2048*2*4)   // 64 KB (A+B stages, 8KB each)

// ---------------- scratch (device globals: allocation-free) ----------------
__device__ __align__(256) __half h_x[M1*DD];          // LN output (fp16)
__device__ __align__(256) float  g_u[M1*DD];          // sigmoid gate
__device__ __align__(256) float  g_r[M1*DD];          // silu gate
__device__ __align__(256) __half h_q2[M1*ZB];         // [q*scale | rot(alpha)]
__device__ __align__(256) __half h_k2[M1*ZB];         // [k       | rot(beta) ]
__device__ __align__(256) __half h_vT[(size_t)BB*DD*CCdim]; // silu(v) transposed [b][e][c]
__device__ __align__(256) __half h_hx[M1*DD];         // (attn@v) * r  (fp16)
__device__ __align__(256) float  g_qk[(size_t)BB*LL*CCdim];  // scores fp32
__device__ __align__(256) __half h_p[(size_t)BB*LL*CCdim];   // probs fp16
__device__ __align__(256) __half h_wq[EE*DD];
__device__ __align__(256) __half h_wk[ZZ*DD];
__device__ __align__(256) __half h_wv[DD*DD];
__device__ __align__(256) __half h_wh[DD*DD];
__device__ __align__(256) __half h_kin[M1*DD];
__device__ __align__(256) __half h_vin[M1*DD];

__device__ __forceinline__ float sigmoidf_(float v){ return 1.f/(1.f+expf(-v)); }
__device__ __forceinline__ float siluf_(float v){ return v/(1.f+expf(-v)); }

__device__ __forceinline__ void mma16(float c[4], const uint32_t a[4], const uint32_t b[2]){
    asm volatile("mma.sync.aligned.m16n8k16.row.col.f32.f16.f16.f32 "
        "{%0,%1,%2,%3}, {%4,%5,%6,%7}, {%8,%9}, {%0,%1,%2,%3};\n"
        : "+f"(c[0]), "+f"(c[1]), "+f"(c[2]), "+f"(c[3])
        : "r"(a[0]), "r"(a[1]), "r"(a[2]), "r"(a[3]), "r"(b[0]), "r"(b[1]));
}
__device__ __forceinline__ void ldsm4(uint32_t r[4], uint32_t addr){
    asm volatile("ldmatrix.sync.aligned.m8n8.x4.shared.b16 {%0,%1,%2,%3}, [%4];"
        : "=r"(r[0]), "=r"(r[1]), "=r"(r[2]), "=r"(r[3]) : "r"(addr));
}
__device__ __forceinline__ void cpa16(uint32_t s, const __half* g){
    asm volatile("cp.async.cg.shared.global [%0], [%1], 16;\n" :: "r"(s), "l"(g));
}
__device__ __forceinline__ void cpa_commit(){ asm volatile("cp.async.commit_group;\n"); }
template<int N>
__device__ __forceinline__ void cpa_wait(){ asm volatile("cp.async.wait_group %0;\n" :: "n"(N)); }

// ---------------- fp32 -> fp16 (8 elems/thread) ----------------
__global__ void f2h_kernel(const float* __restrict__ in, __half* __restrict__ out)
{
    long i = ((long)blockIdx.x*256 + threadIdx.x) * 8;
    float4 a = *(const float4*)(in + i);
    float4 b = *(const float4*)(in + i + 4);
    __half2 r[4];
    r[0] = __floats2half2_rn(a.x, a.y);
    r[1] = __floats2half2_rn(a.z, a.w);
    r[2] = __floats2half2_rn(b.x, b.y);
    r[3] = __floats2half2_rn(b.z, b.w);
    *(uint4*)(out + i) = *(uint4*)r;
}

// ---------------- LayerNorm -> fp16 ----------------
__global__ void ln_kernel(const float* __restrict__ q, const float* __restrict__ w,
                          const float* __restrict__ b, __half* __restrict__ x)
{
    int row = blockIdx.x;
    int tid = threadIdx.x;
    const float4* p = (const float4*)(q + (size_t)row*DD);
    float4 v = p[tid];
    float s  = v.x+v.y+v.z+v.w;
    float ss = v.x*v.x+v.y*v.y+v.z*v.z+v.w*v.w;
    #pragma unroll
    for (int o=16;o;o>>=1){ s += __shfl_xor_sync(~0u,s,o); ss += __shfl_xor_sync(~0u,ss,o); }
    __shared__ float shA[8], shB[8];
    int warp = tid>>5, lane = tid&31;
    if (lane==0){ shA[warp]=s; shB[warp]=ss; }
    __syncthreads();
    float tots=0.f, totss=0.f;
    #pragma unroll
    for (int wdx=0; wdx<8; ++wdx){ tots += shA[wdx]; totss += shB[wdx]; }
    float mean = tots*(1.f/DD);
    float var  = totss*(1.f/DD) - mean*mean;
    float rstd = rsqrtf(var + 1e-5f);
    float4 w4 = ((const float4*)w)[tid];
    float4 b4 = ((const float4*)b)[tid];
    __half2 o0 = __floats2half2_rn((v.x-mean)*rstd*w4.x + b4.x, (v.y-mean)*rstd*w4.y + b4.y);
    __half2 o1 = __floats2half2_rn((v.z-mean)*rstd*w4.z + b4.z, (v.w-mean)*rstd*w4.w + b4.w);
    __half2* op = (__half2*)(x + (size_t)row*DD);
    op[tid*2]   = o0;
    op[tid*2+1] = o1;
}

// ---------------- rotary tables -> bias columns of h_q2 / h_k2 ----------------
__global__ void rotab_kernel(const float* __restrict__ alpha, const float* __restrict__ beta)
{
    int m = blockIdx.x;        // l or c index, 0..2047
    int i = threadIdx.x;       // 0..63
    float f = expf((float)i * (-9.210340371976184f / 64.f));
    float ang = (float)m * f;
    float s, c;
    sincosf(ang, &s, &c);
    float a1 = alpha[i], a2 = alpha[i+64];
    __half ar0 = __float2half_rn(a1*c - a2*s);
    __half ar1 = __float2half_rn(a2*c + a1*s);
    float b1 = beta[i],  b2 = beta[i+64];
    __half br0 = __float2half_rn(b1*c - b2*s);
    __half br1 = __float2half_rn(b2*c + b1*s);
    #pragma unroll
    for (int b=0;b<BB;++b) {
        long row = (long)(m*BB + b) * ZB + ZZ;
        h_q2[row + i]      = ar0;
        h_q2[row + i + 64] = ar1;
        h_k2[row + i]      = br0;
        h_k2[row + i + 64] = br1;
    }
}

// ---------------- softmax (fp32 scores, bias already in scores) -> fp16 probs ----------------
__global__ void softmax_kernel()
{
    long row = blockIdx.x;
    const float* p = g_qk + row * (long)CCdim;
    __half* hp = h_p + row * (long)CCdim;
    int tid = threadIdx.x;
    float4 v0 = ((const float4*)p)[tid];
    float4 v1 = ((const float4*)p)[tid+256];
    float e0=v0.x, e1=v0.y, e2=v0.z, e3=v0.w, e4=v1.x, e5=v1.y, e6=v1.z, e7=v1.w;
    float mx = fmaxf(fmaxf(fmaxf(e0,e1),fmaxf(e2,e3)), fmaxf(fmaxf(e4,e5),fmaxf(e6,e7)));
    #pragma unroll
    for (int o=16;o;o>>=1) mx = fmaxf(mx, __shfl_xor_sync(~0u,mx,o));
    __shared__ float shm[8], shs[8];
    int warp = tid>>5, lane = tid&31;
    if (lane==0) shm[warp] = mx;
    __syncthreads();
    mx = shm[0];
    #pragma unroll
    for (int wdx=1; wdx<8; ++wdx) mx = fmaxf(mx, shm[wdx]);
    e0 = expf(e0-mx); e1 = expf(e1-mx); e2 = expf(e2-mx); e3 = expf(e3-mx);
    e4 = expf(e4-mx); e5 = expf(e5-mx); e6 = expf(e6-mx); e7 = expf(e7-mx);
    float s = e0+e1+e2+e3+e4+e5+e6+e7;
    #pragma unroll
    for (int o=16;o;o>>=1) s += __shfl_xor_sync(~0u,s,o);
    if (lane==0) shs[warp] = s;
    __syncthreads();
    s = 0.f;
    #pragma unroll
    for (int wdx=0; wdx<8; ++wdx) s += shs[wdx];
    float inv = 1.f/s;
    __half2 r0[2], r1[2];
    r0[0] = __floats2half2_rn(e0*inv, e1*inv);
    r0[1] = __floats2half2_rn(e2*inv, e3*inv);
    r1[0] = __floats2half2_rn(e4*inv, e5*inv);
    r1[1] = __floats2half2_rn(e6*inv, e7*inv);
    ((uint2*)hp)[tid]     = *(uint2*)r0;
    ((uint2*)hp)[tid+256] = *(uint2*)r1;
}

// ---------------- FP16 GEMM, 128x128x32, 4-stage cp.async, ldmatrix fragments ----------------
// smem stage: [row(128)][16 uint32] rows of 64B; 16B chunk c swizzled c ^= (row>>1)&3
// (verified ldmatrix-conflict-free: even/odd rows hit opposite 16-bank halves,
//  same-half rows get distinct chunks).
// MODE 0: base proj -> g_u/g_r/h_q2.  1: fp32 store (QK).  2: half(v+aux1[n]) (k proj).
// 4: gated residual out (fp32).  5: half(silu(v+aux1[m])) (V^T proj).
// 6: half(v * aux2[idx]) (attn@V with fused h*r).
template<int MODE>
__global__ void __launch_bounds__(256, 2)
gemm_h(const __half* __restrict__ A, const __half* __restrict__ Bm,
       int K, int lda, int ldb, long sAz, long sBz,
       float* __restrict__ CF, __half* __restrict__ CH, int ldc, long sCz,
       const float* __restrict__ aux1, const float* __restrict__ aux2)
{
    extern __shared__ uint32_t smem[];
    uint32_t* As = smem;                   // STAGES * 2048 units
    uint32_t* Bs = smem + STAGES*2048;
    uint32_t AsU = (uint32_t)__cvta_generic_to_shared(As);
    uint32_t BsU = (uint32_t)__cvta_generic_to_shared(Bs);

    const int bz = blockIdx.z;
    A  += (long)bz * sAz;
    Bm += (long)bz * sBz;

    const int m0 = blockIdx.y << 7, n0 = blockIdx.x << 7;
    const int tid = threadIdx.x, lane = tid & 31, wid = tid >> 5;
    const int wm4 = (wid >> 2) << 2;   // m16-tile base: 0 or 4
    const int wn4 = (wid & 3) << 2;    // n8-tile base: 0,4,8,12

    float acc[4][4][4];
    #pragma unroll
    for (int i=0;i<4;++i)
        #pragma unroll
        for (int j=0;j<4;++j)
            #pragma unroll
            for (int c=0;c<4;++c) acc[i][j][c] = 0.f;

    // ---- cp.async loaders: 2 chunks (16B) per thread per operand ----
    const int ar0 = tid >> 2, ac0 = tid & 3;
    const __half* ga0 = A + (long)(m0 + ar0)*lda + ac0*8;
    const __half* ga1 = ga0 + (long)64*lda;
    const uint32_t sa0 = (uint32_t)(ar0*16      + ((ac0 ^ ((ar0>>1)&3))<<2)) * 4;
    const uint32_t sa1 = (uint32_t)((ar0+64)*16 + ((ac0 ^ (((ar0+64)>>1)&3))<<2)) * 4;
    const __half* gb0 = Bm + (long)(n0 + ar0)*ldb + ac0*8;
    const __half* gb1 = gb0 + (long)64*ldb;

    // ---- ldmatrix per-lane fragment base addresses (byte offsets within a stage) ----
    // A x4: lanes 0-7 rows+0..7 ch0 | 8-15 rows+8..15 ch0 | 16-23 rows ch1 | 24-31 rows+8 ch1
    const int arow = wm4*16 + (lane & 7) + ((lane >> 3) & 1) * 8;
    const int ach  = (lane >> 4) & 1;
    const uint32_t aFrag = (uint32_t)(arow*16 + ((ach ^ ((arow>>1)&3))<<2)) * 4;
    // B x4 (covers 2 n8-tiles): lanes 0-7 n-rows+0..7 ch0 | 8-15 same rows ch1 | 16-23 rows+8 ch0 | 24-31 rows+8 ch1
    const int brow = wn4*8 + ((lane >> 4) & 1) * 8 + (lane & 7);
    const int bch  = (lane >> 3) & 1;
    const uint32_t bFrag = (uint32_t)(brow*16 + ((bch ^ ((brow>>1)&3))<<2)) * 4;

    const int ktiles = K >> 5;             // KT = 32 halves

    auto load_tile = [&](int slot, int kt){
        uint32_t aB = AsU + (uint32_t)slot*2048*4;
        uint32_t bB = BsU + (uint32_t)slot*2048*4;
        cpa16(aB + sa0, ga0 + kt*32);
        cpa16(aB + sa1, ga1 + kt*32);
        cpa16(bB + sa0, gb0 + kt*32);
        cpa16(bB + sa1, gb1 + kt*32);
    };

    auto comp = [&](int slot){
        uint32_t aB = AsU + (uint32_t)slot*2048*4 + aFrag;
        uint32_t bB = BsU + (uint32_t)slot*2048*4 + bFrag;
        #pragma unroll
        for (int ks=0; ks<2; ++ks) {
            uint32_t af[4][4], bf[4][4];   // bf[np] = {b[2np][0], b[2np][1], b[2np+1][0], b[2np+1][1]}
            #pragma unroll
            for (int mt=0; mt<4; ++mt)
                ldsm4(af[mt], (aB + mt*1024) ^ (ks<<5));
            #pragma unroll
            for (int np=0; np<2; ++np)
                ldsm4(bf[np], (bB + np*1024) ^ (ks<<5));
            #pragma unroll
            for (int mt=0; mt<4; ++mt)
                #pragma unroll
                for (int nt=0; nt<4; ++nt)
                    mma16(acc[mt][nt], af[mt], &bf[nt>>1][(nt&1)<<1]);
        }
    };

    #pragma unroll
    for (int s=0; s<STAGES-1; ++s) { load_tile(s, s); cpa_commit(); }

    for (int kt=0; kt<ktiles; ++kt) {
        cpa_wait<STAGES-2>();
        __syncthreads();
        int nk = kt + STAGES - 1;
        if (nk < ktiles) load_tile(nk & (STAGES-1), nk);
        cpa_commit();
        comp(kt & (STAGES-1));
    }

    // ---- epilogue ----
    #pragma unroll
    for (int mt=0; mt<4; ++mt) {
        #pragma unroll
        for (int ci2=0; ci2<2; ++ci2) {
            int m = m0 + (wm4+mt)*16 + (lane>>2) + ci2*8;
            #pragma unroll
            for (int nt=0; nt<4; ++nt) {
                #pragma unroll
                for (int cj=0; cj<2; ++cj) {
                    int n = n0 + (wn4+nt)*8 + ((lane&3)<<1) + cj;
                    float v = acc[mt][nt][ci2*2+cj];
                    if (MODE==0) {
                        v += aux1[n];
                        if (n < DD)            g_u[(long)m*DD + n]        = sigmoidf_(v);
                        else if (n < 2*DD)     g_r[(long)m*DD + (n-DD)]   = siluf_(v);
                        else                   h_q2[(long)m*ZB + (n-2*DD)] = __float2half_rn(v * 0.08838834764831845f);
                    } else if (MODE==1) {
                        CF[(long)m*ldc + n + (long)bz*sCz] = v;
                    } else if (MODE==2) {
                        CH[(long)m*ldc + n + (long)bz*sCz] = __float2half_rn(v + aux1[n]);
                    } else if (MODE==5) {
                        CH[(long)m*ldc + n + (long)bz*sCz] = __float2half_rn(siluf_(v + aux1[m]));
                    } else if (MODE==6) {
                        long idx = (long)m*ldc + n + (long)bz*sCz;
                        CH[idx] = __float2half_rn(v * aux2[idx]);
                    } else { // MODE 4
                        float t = siluf_(v + aux1[n]);
                        long idx = (long)m*DD + n;
                        float res = aux2[idx];
                        CF[idx] = res + g_u[idx]*(t - res);
                    }
                }
            }
        }
    }
}

// ---------------- launch ----------------
extern "C" void kernel_launch(void* const* d_in, const int* in_sizes, int n_in,
                              void* d_out, int out_size)
{
    const float* query   = (const float*)d_in[0];
    const float* key_seq = (const float*)d_in[1];
    const float* value   = (const float*)d_in[2];
    const float* wq      = (const float*)d_in[3];
    const float* bq      = (const float*)d_in[4];
    const float* wk      = (const float*)d_in[5];
    const float* bk      = (const float*)d_in[6];
    const float* wv      = (const float*)d_in[7];
    const float* bv      = (const float*)d_in[8];
    const float* wh      = (const float*)d_in[9];
    const float* bh      = (const float*)d_in[10];
    const float* ln_w    = (const float*)d_in[11];
    const float* ln_b    = (const float*)d_in[12];
    const float* alpha   = (const float*)d_in[13];
    const float* beta    = (const float*)d_in[14];
    float* out = (float*)d_out;

    __half *p_wq, *p_wk, *p_wv, *p_wh, *p_kin, *p_vin, *p_x, *p_q2, *p_k2, *p_vT, *p_hx, *p_p;
    float *p_r, *p_qk;
    cudaGetSymbolAddress((void**)&p_wq,  h_wq);
    cudaGetSymbolAddress((void**)&p_wk,  h_wk);
    cudaGetSymbolAddress((void**)&p_wv,  h_wv);
    cudaGetSymbolAddress((void**)&p_wh,  h_wh);
    cudaGetSymbolAddress((void**)&p_kin, h_kin);
    cudaGetSymbolAddress((void**)&p_vin, h_vin);
    cudaGetSymbolAddress((void**)&p_x,   h_x);
    cudaGetSymbolAddress((void**)&p_q2,  h_q2);
    cudaGetSymbolAddress((void**)&p_k2,  h_k2);
    cudaGetSymbolAddress((void**)&p_vT,  h_vT);
    cudaGetSymbolAddress((void**)&p_hx,  h_hx);
    cudaGetSymbolAddress((void**)&p_p,   h_p);
    cudaGetSymbolAddress((void**)&p_r,   g_r);
    cudaGetSymbolAddress((void**)&p_qk,  g_qk);

    static bool attr_done = false;
    if (!attr_done) {
        cudaFuncSetAttribute((const void*)gemm_h<0>, cudaFuncAttributeMaxDynamicSharedMemorySize, SMEM_BYTES);
        cudaFuncSetAttribute((const void*)gemm_h<1>, cudaFuncAttributeMaxDynamicSharedMemorySize, SMEM_BYTES);
        cudaFuncSetAttribute((const void*)gemm_h<2>, cudaFuncAttributeMaxDynamicSharedMemorySize, SMEM_BYTES);
        cudaFuncSetAttribute((const void*)gemm_h<4>, cudaFuncAttributeMaxDynamicSharedMemorySize, SMEM_BYTES);
        cudaFuncSetAttribute((const void*)gemm_h<5>, cudaFuncAttributeMaxDynamicSharedMemorySize, SMEM_BYTES);
        cudaFuncSetAttribute((const void*)gemm_h<6>, cudaFuncAttributeMaxDynamicSharedMemorySize, SMEM_BYTES);
        attr_done = true;
    }

    // 0. fp32 -> fp16 conversions
    f2h_kernel<<<EE*DD/2048, 256>>>(wq, p_wq);
    f2h_kernel<<<ZZ*DD/2048, 256>>>(wk, p_wk);
    f2h_kernel<<<DD*DD/2048, 256>>>(wv, p_wv);
    f2h_kernel<<<DD*DD/2048, 256>>>(wh, p_wh);
    f2h_kernel<<<M1*DD/2048, 256>>>(key_seq, p_kin);
    f2h_kernel<<<M1*DD/2048, 256>>>(value, p_vin);
    // 1. LayerNorm -> fp16
    ln_kernel<<<M1, 256>>>(query, ln_w, ln_b, p_x);
    // 2. rotary tables -> bias columns of h_q2 / h_k2
    rotab_kernel<<<LL, 64>>>(alpha, beta);
    // 3. base projection: u/r/q (8192 x 2176 x 1024); q lands in h_q2[:, :128]
    gemm_h<0><<<dim3(EE/128, M1/128, 1), 256, SMEM_BYTES>>>(
        p_x, p_wq, DD, DD, DD, 0, 0, nullptr, nullptr, 0, 0, bq, nullptr);
    // 4. k projection (8192 x 128 x 1024) -> h_k2[:, :128]
    gemm_h<2><<<dim3(1, M1/128, 1), 256, SMEM_BYTES>>>(
        p_kin, p_wk, DD, DD, DD, 0, 0, nullptr, p_k2, ZB, 0, bk, nullptr);
    // 5. V projection TRANSPOSED: vT[b][e][c] = silu(wv[e,:]·value[c,b,:] + bv[e])
    gemm_h<5><<<dim3(CCdim/128, DD/128, BB), 256, SMEM_BYTES>>>(
        p_wv, p_vin, DD, DD, BB*DD, 0, (long)DD,
        nullptr, p_vT, CCdim, (long)DD*CCdim, bv, nullptr);
    // 6. QK^T + rotary bias fused as K=256 GEMM -> fp32 scores
    gemm_h<1><<<dim3(CCdim/128, LL/128, BB), 256, SMEM_BYTES>>>(
        p_q2, p_k2, ZB, BB*ZB, BB*ZB, (long)ZB, (long)ZB,
        p_qk, nullptr, CCdim, (long)LL*CCdim, nullptr, nullptr);
    // 7. softmax -> fp16 probs
    softmax_kernel<<<BB*LL, 256>>>();
    // 8. attn @ V batched with fused *r -> fp16 h_hx  (idx of Cout == idx of g_r)
    gemm_h<6><<<dim3(DD/128, LL/128, BB), 256, SMEM_BYTES>>>(
        p_p, p_vT, CCdim, CCdim, CCdim, (long)LL*CCdim, (long)DD*CCdim,
        nullptr, p_hx, BB*DD, (long)DD, nullptr, p_r);
    // 9. output projection + silu + gated residual (fp32 out)
    gemm_h<4><<<dim3(DD/128, M1/128, 1), 256, SMEM_BYTES>>>(
        p_hx, p_wh, DD, DD, DD, 0, 0, out, nullptr, DD, 0, bh, query);
}

// round 14
// speedup vs baseline: 1.3209x; 1.0007x over previous
#include <cuda_runtime.h>
#include <cuda_fp16.h>
#include <math.h>
#include <stdint.h>

#define LL 2048
#define CCdim 2048
#define BB 4
#define DD 1024
#define ZZ 128
#define EE (2*DD+ZZ)   // 2176
#define M1 (LL*BB)     // 8192
#define ZB 256         // fused q/k width (Z + 128 bias cols)

#define STAGES 6
#define SMEM_BYTES (STAGES*2048*2*4)   // 96 KB (A+B stages, 8KB each)

// ---------------- scratch (device globals: allocation-free) ----------------
__device__ __align__(256) __half h_x[M1*DD];          // LN output (fp16)
__device__ __align__(256) float  g_u[M1*DD];          // sigmoid gate
__device__ __align__(256) float  g_r[M1*DD];          // silu gate
__device__ __align__(256) __half h_q2[M1*ZB];         // [q*scale | rot(alpha)]
__device__ __align__(256) __half h_k2[M1*ZB];         // [k       | rot(beta) ]
__device__ __align__(256) __half h_vT[(size_t)BB*DD*CCdim]; // silu(v) transposed [b][e][c]
__device__ __align__(256) __half h_hx[M1*DD];         // (attn@v) * r  (fp16)
__device__ __align__(256) __half h_p[(size_t)BB*LL*CCdim];   // scores -> probs (fp16, in place)
__device__ __align__(256) __half h_wq[EE*DD];
__device__ __align__(256) __half h_wk[ZZ*DD];
__device__ __align__(256) __half h_wv[DD*DD];
__device__ __align__(256) __half h_wh[DD*DD];
__device__ __align__(256) __half h_kin[M1*DD];
__device__ __align__(256) __half h_vin[M1*DD];

__device__ __forceinline__ float sigmoidf_(float v){ return 1.f/(1.f+expf(-v)); }
__device__ __forceinline__ float siluf_(float v){ return v/(1.f+expf(-v)); }

__device__ __forceinline__ void mma16(float c[4], const uint32_t a[4], const uint32_t b[2]){
    asm volatile("mma.sync.aligned.m16n8k16.row.col.f32.f16.f16.f32 "
        "{%0,%1,%2,%3}, {%4,%5,%6,%7}, {%8,%9}, {%0,%1,%2,%3};\n"
        : "+f"(c[0]), "+f"(c[1]), "+f"(c[2]), "+f"(c[3])
        : "r"(a[0]), "r"(a[1]), "r"(a[2]), "r"(a[3]), "r"(b[0]), "r"(b[1]));
}
__device__ __forceinline__ void ldsm4(uint32_t r[4], uint32_t addr){
    asm volatile("ldmatrix.sync.aligned.m8n8.x4.shared.b16 {%0,%1,%2,%3}, [%4];"
        : "=r"(r[0]), "=r"(r[1]), "=r"(r[2]), "=r"(r[3]) : "r"(addr));
}
__device__ __forceinline__ void cpa16(uint32_t s, const __half* g){
    asm volatile("cp.async.cg.shared.global [%0], [%1], 16;\n" :: "r"(s), "l"(g));
}
__device__ __forceinline__ void cpa_commit(){ asm volatile("cp.async.commit_group;\n"); }
template<int N>
__device__ __forceinline__ void cpa_wait(){ asm volatile("cp.async.wait_group %0;\n" :: "n"(N)); }

// ---------------- single fused fp32->fp16 pass over all 6 arrays ----------------
// block ranges: wq 1088 | wk 64 | wv 512 | wh 512 | kin 4096 | vin 4096  (8 elems/thread)
__global__ void f2h_all(const float* __restrict__ wq,  __half* __restrict__ owq,
                        const float* __restrict__ wk,  __half* __restrict__ owk,
                        const float* __restrict__ wv,  __half* __restrict__ owv,
                        const float* __restrict__ wh,  __half* __restrict__ owh,
                        const float* __restrict__ ki,  __half* __restrict__ oki,
                        const float* __restrict__ vi,  __half* __restrict__ ovi)
{
    int b = blockIdx.x;
    const float* in; __half* out; long base;
    if      (b < 1088) { in = wq; out = owq; base = b; }
    else if (b < 1152) { in = wk; out = owk; base = b - 1088; }
    else if (b < 1664) { in = wv; out = owv; base = b - 1152; }
    else if (b < 2176) { in = wh; out = owh; base = b - 1664; }
    else if (b < 6272) { in = ki; out = oki; base = b - 2176; }
    else               { in = vi; out = ovi; base = b - 6272; }
    long i = (base*256 + threadIdx.x) * 8;
    float4 a = *(const float4*)(in + i);
    float4 c = *(const float4*)(in + i + 4);
    __half2 r[4];
    r[0] = __floats2half2_rn(a.x, a.y);
    r[1] = __floats2half2_rn(a.z, a.w);
    r[2] = __floats2half2_rn(c.x, c.y);
    r[3] = __floats2half2_rn(c.z, c.w);
    *(uint4*)(out + i) = *(uint4*)r;
}

// ---------------- LayerNorm -> fp16 ----------------
__global__ void ln_kernel(const float* __restrict__ q, const float* __restrict__ w,
                          const float* __restrict__ b, __half* __restrict__ x)
{
    int row = blockIdx.x;
    int tid = threadIdx.x;
    const float4* p = (const float4*)(q + (size_t)row*DD);
    float4 v = p[tid];
    float s  = v.x+v.y+v.z+v.w;
    float ss = v.x*v.x+v.y*v.y+v.z*v.z+v.w*v.w;
    #pragma unroll
    for (int o=16;o;o>>=1){ s += __shfl_xor_sync(~0u,s,o); ss += __shfl_xor_sync(~0u,ss,o); }
    __shared__ float shA[8], shB[8];
    int warp = tid>>5, lane = tid&31;
    if (lane==0){ shA[warp]=s; shB[warp]=ss; }
    __syncthreads();
    float tots=0.f, totss=0.f;
    #pragma unroll
    for (int wdx=0; wdx<8; ++wdx){ tots += shA[wdx]; totss += shB[wdx]; }
    float mean = tots*(1.f/DD);
    float var  = totss*(1.f/DD) - mean*mean;
    float rstd = rsqrtf(var + 1e-5f);
    float4 w4 = ((const float4*)w)[tid];
    float4 b4 = ((const float4*)b)[tid];
    __half2 o0 = __floats2half2_rn((v.x-mean)*rstd*w4.x + b4.x, (v.y-mean)*rstd*w4.y + b4.y);
    __half2 o1 = __floats2half2_rn((v.z-mean)*rstd*w4.z + b4.z, (v.w-mean)*rstd*w4.w + b4.w);
    __half2* op = (__half2*)(x + (size_t)row*DD);
    op[tid*2]   = o0;
    op[tid*2+1] = o1;
}

// ---------------- rotary tables -> bias columns of h_q2 / h_k2 ----------------
__global__ void rotab_kernel(const float* __restrict__ alpha, const float* __restrict__ beta)
{
    int m = blockIdx.x;        // 0..2047
    int i = threadIdx.x;       // 0..63
    float f = expf((float)i * (-9.210340371976184f / 64.f));
    float ang = (float)m * f;
    float s, c;
    sincosf(ang, &s, &c);
    float a1 = alpha[i], a2 = alpha[i+64];
    __half ar0 = __float2half_rn(a1*c - a2*s);
    __half ar1 = __float2half_rn(a2*c + a1*s);
    float b1 = beta[i],  b2 = beta[i+64];
    __half br0 = __float2half_rn(b1*c - b2*s);
    __half br1 = __float2half_rn(b2*c + b1*s);
    #pragma unroll
    for (int b=0;b<BB;++b) {
        long row = (long)(m*BB + b) * ZB + ZZ;
        h_q2[row + i]      = ar0;
        h_q2[row + i + 64] = ar1;
        h_k2[row + i]      = br0;
        h_k2[row + i + 64] = br1;
    }
}

// ---------------- softmax in place on fp16 h_p ----------------
__global__ void softmax_kernel()
{
    long row = blockIdx.x;
    __half* hp = h_p + row * (long)CCdim;
    int tid = threadIdx.x;                 // 256 threads * 8 halves = 2048
    uint4 raw = ((const uint4*)hp)[tid];
    __half2* hv = (__half2*)&raw;
    float2 f0 = __half22float2(hv[0]);
    float2 f1 = __half22float2(hv[1]);
    float2 f2 = __half22float2(hv[2]);
    float2 f3 = __half22float2(hv[3]);
    float e0=f0.x, e1=f0.y, e2=f1.x, e3=f1.y, e4=f2.x, e5=f2.y, e6=f3.x, e7=f3.y;
    float mx = fmaxf(fmaxf(fmaxf(e0,e1),fmaxf(e2,e3)), fmaxf(fmaxf(e4,e5),fmaxf(e6,e7)));
    #pragma unroll
    for (int o=16;o;o>>=1) mx = fmaxf(mx, __shfl_xor_sync(~0u,mx,o));
    __shared__ float shm[8], shs[8];
    int warp = tid>>5, lane = tid&31;
    if (lane==0) shm[warp] = mx;
    __syncthreads();
    mx = shm[0];
    #pragma unroll
    for (int wdx=1; wdx<8; ++wdx) mx = fmaxf(mx, shm[wdx]);
    e0 = expf(e0-mx); e1 = expf(e1-mx); e2 = expf(e2-mx); e3 = expf(e3-mx);
    e4 = expf(e4-mx); e5 = expf(e5-mx); e6 = expf(e6-mx); e7 = expf(e7-mx);
    float s = e0+e1+e2+e3+e4+e5+e6+e7;
    #pragma unroll
    for (int o=16;o;o>>=1) s += __shfl_xor_sync(~0u,s,o);
    if (lane==0) shs[warp] = s;
    __syncthreads();
    s = 0.f;
    #pragma unroll
    for (int wdx=0; wdx<8; ++wdx) s += shs[wdx];
    float inv = 1.f/s;
    __half2 r[4];
    r[0] = __floats2half2_rn(e0*inv, e1*inv);
    r[1] = __floats2half2_rn(e2*inv, e3*inv);
    r[2] = __floats2half2_rn(e4*inv, e5*inv);
    r[3] = __floats2half2_rn(e6*inv, e7*inv);
    ((uint4*)hp)[tid] = *(uint4*)r;
}

// ---------------- FP16 GEMM, 128x128x32, 6-stage cp.async (paired), ldmatrix ----------------
// smem stage: [row(128)][16 uint32] rows of 64B; 16B chunk c swizzled c ^= (row>>1)&3.
// Mainloop consumes stages in PAIRS (2 k-tiles per wait/sync/commit) — halves barrier count.
// MODE 0: base proj -> g_u/g_r/h_q2.  2: half(v+aux1[n]) (k proj).  4: gated residual (fp32).
// 5: half(silu(v+aux1[m])) (V^T proj). 6: half(v*aux2[idx]) (attn@V, fused *r). 7: half(v) (QK scores).
template<int MODE>
__global__ void __launch_bounds__(256, 2)
gemm_h(const __half* __restrict__ A, const __half* __restrict__ Bm,
       int K, int lda, int ldb, long sAz, long sBz,
       float* __restrict__ CF, __half* __restrict__ CH, int ldc, long sCz,
       const float* __restrict__ aux1, const float* __restrict__ aux2)
{
    extern __shared__ uint32_t smem[];
    uint32_t* As = smem;                   // STAGES * 2048 units
    uint32_t* Bs = smem + STAGES*2048;
    uint32_t AsU = (uint32_t)__cvta_generic_to_shared(As);
    uint32_t BsU = (uint32_t)__cvta_generic_to_shared(Bs);

    const int bz = blockIdx.z;
    A  += (long)bz * sAz;
    Bm += (long)bz * sBz;

    const int m0 = blockIdx.y << 7, n0 = blockIdx.x << 7;
    const int tid = threadIdx.x, lane = tid & 31, wid = tid >> 5;
    const int wm4 = (wid >> 2) << 2;
    const int wn4 = (wid & 3) << 2;

    float acc[4][4][4];
    #pragma unroll
    for (int i=0;i<4;++i)
        #pragma unroll
        for (int j=0;j<4;++j)
            #pragma unroll
            for (int c=0;c<4;++c) acc[i][j][c] = 0.f;

    // ---- cp.async loaders ----
    const int ar0 = tid >> 2, ac0 = tid & 3;
    const __half* ga0 = A + (long)(m0 + ar0)*lda + ac0*8;
    const __half* ga1 = ga0 + (long)64*lda;
    const uint32_t sa0 = (uint32_t)(ar0*16      + ((ac0 ^ ((ar0>>1)&3))<<2)) * 4;
    const uint32_t sa1 = (uint32_t)((ar0+64)*16 + ((ac0 ^ (((ar0+64)>>1)&3))<<2)) * 4;
    const __half* gb0 = Bm + (long)(n0 + ar0)*ldb + ac0*8;
    const __half* gb1 = gb0 + (long)64*ldb;

    // ---- ldmatrix per-lane fragment bases ----
    const int arow = wm4*16 + (lane & 7) + ((lane >> 3) & 1) * 8;
    const int ach  = (lane >> 4) & 1;
    const uint32_t aFrag = (uint32_t)(arow*16 + ((ach ^ ((arow>>1)&3))<<2)) * 4;
    const int brow = wn4*8 + ((lane >> 4) & 1) * 8 + (lane & 7);
    const int bch  = (lane >> 3) & 1;
    const uint32_t bFrag = (uint32_t)(brow*16 + ((bch ^ ((brow>>1)&3))<<2)) * 4;

    const int ktiles = K >> 5;             // even for all our K
    const int npairs = ktiles >> 1;

    auto load_tile = [&](int slot, int kt){
        uint32_t aB = AsU + (uint32_t)slot*2048*4;
        uint32_t bB = BsU + (uint32_t)slot*2048*4;
        cpa16(aB + sa0, ga0 + kt*32);
        cpa16(aB + sa1, ga1 + kt*32);
        cpa16(bB + sa0, gb0 + kt*32);
        cpa16(bB + sa1, gb1 + kt*32);
    };

    auto comp = [&](int slot){
        uint32_t aB = AsU + (uint32_t)slot*2048*4 + aFrag;
        uint32_t bB = BsU + (uint32_t)slot*2048*4 + bFrag;
        #pragma unroll
        for (int ks=0; ks<2; ++ks) {
            uint32_t af[4][4], bf[2][4];
            #pragma unroll
            for (int mt=0; mt<4; ++mt)
                ldsm4(af[mt], (aB + mt*1024) ^ (ks<<5));
            #pragma unroll
            for (int np=0; np<2; ++np)
                ldsm4(bf[np], (bB + np*1024) ^ (ks<<5));
            #pragma unroll
            for (int mt=0; mt<4; ++mt)
                #pragma unroll
                for (int nt=0; nt<4; ++nt)
                    mma16(acc[mt][nt], af[mt], &bf[nt>>1][(nt&1)<<1]);
        }
    };

    // prologue: pairs 0 and 1 (tiles 0..3), one commit group per pair
    load_tile(0, 0); load_tile(1, 1); cpa_commit();
    load_tile(2, 2); load_tile(3, 3); cpa_commit();

    for (int p=0; p<npairs; ++p) {
        cpa_wait<1>();                     // pair p landed
        __syncthreads();                   // everyone done reading pair p-1's slots
        int np = p + 2;
        if (np < npairs) {
            int s0 = (2*np) % STAGES;
            load_tile(s0, 2*np); load_tile(s0+1, 2*np+1);
        }
        cpa_commit();
        int c0 = (2*p) % STAGES;
        comp(c0); comp(c0+1);
    }

    // ---- epilogue ----
    #pragma unroll
    for (int mt=0; mt<4; ++mt) {
        #pragma unroll
        for (int ci2=0; ci2<2; ++ci2) {
            int m = m0 + (wm4+mt)*16 + (lane>>2) + ci2*8;
            #pragma unroll
            for (int nt=0; nt<4; ++nt) {
                #pragma unroll
                for (int cj=0; cj<2; ++cj) {
                    int n = n0 + (wn4+nt)*8 + ((lane&3)<<1) + cj;
                    float v = acc[mt][nt][ci2*2+cj];
                    if (MODE==0) {
                        v += aux1[n];
                        if (n < DD)            g_u[(long)m*DD + n]        = sigmoidf_(v);
                        else if (n < 2*DD)     g_r[(long)m*DD + (n-DD)]   = siluf_(v);
                        else                   h_q2[(long)m*ZB + (n-2*DD)] = __float2half_rn(v * 0.08838834764831845f);
                    } else if (MODE==2) {
                        CH[(long)m*ldc + n + (long)bz*sCz] = __float2half_rn(v + aux1[n]);
                    } else if (MODE==5) {
                        CH[(long)m*ldc + n + (long)bz*sCz] = __float2half_rn(siluf_(v + aux1[m]));
                    } else if (MODE==6) {
                        long idx = (long)m*ldc + n + (long)bz*sCz;
                        CH[idx] = __float2half_rn(v * aux2[idx]);
                    } else if (MODE==7) {
                        CH[(long)m*ldc + n + (long)bz*sCz] = __float2half_rn(v);
                    } else { // MODE 4
                        float t = siluf_(v + aux1[n]);
                        long idx = (long)m*DD + n;
                        float res = aux2[idx];
                        CF[idx] = res + g_u[idx]*(t - res);
                    }
                }
            }
        }
    }
}

// ---------------- launch ----------------
extern "C" void kernel_launch(void* const* d_in, const int* in_sizes, int n_in,
                              void* d_out, int out_size)
{
    const float* query   = (const float*)d_in[0];
    const float* key_seq = (const float*)d_in[1];
    const float* value   = (const float*)d_in[2];
    const float* wq      = (const float*)d_in[3];
    const float* bq      = (const float*)d_in[4];
    const float* wk      = (const float*)d_in[5];
    const float* bk      = (const float*)d_in[6];
    const float* wv      = (const float*)d_in[7];
    const float* bv      = (const float*)d_in[8];
    const float* wh      = (const float*)d_in[9];
    const float* bh      = (const float*)d_in[10];
    const float* ln_w    = (const float*)d_in[11];
    const float* ln_b    = (const float*)d_in[12];
    const float* alpha   = (const float*)d_in[13];
    const float* beta    = (const float*)d_in[14];
    float* out = (float*)d_out;

    __half *p_wq, *p_wk, *p_wv, *p_wh, *p_kin, *p_vin, *p_x, *p_q2, *p_k2, *p_vT, *p_hx, *p_p;
    float *p_r;
    cudaGetSymbolAddress((void**)&p_wq,  h_wq);
    cudaGetSymbolAddress((void**)&p_wk,  h_wk);
    cudaGetSymbolAddress((void**)&p_wv,  h_wv);
    cudaGetSymbolAddress((void**)&p_wh,  h_wh);
    cudaGetSymbolAddress((void**)&p_kin, h_kin);
    cudaGetSymbolAddress((void**)&p_vin, h_vin);
    cudaGetSymbolAddress((void**)&p_x,   h_x);
    cudaGetSymbolAddress((void**)&p_q2,  h_q2);
    cudaGetSymbolAddress((void**)&p_k2,  h_k2);
    cudaGetSymbolAddress((void**)&p_vT,  h_vT);
    cudaGetSymbolAddress((void**)&p_hx,  h_hx);
    cudaGetSymbolAddress((void**)&p_p,   h_p);
    cudaGetSymbolAddress((void**)&p_r,   g_r);

    static bool attr_done = false;
    if (!attr_done) {
        cudaFuncSetAttribute((const void*)gemm_h<0>, cudaFuncAttributeMaxDynamicSharedMemorySize, SMEM_BYTES);
        cudaFuncSetAttribute((const void*)gemm_h<2>, cudaFuncAttributeMaxDynamicSharedMemorySize, SMEM_BYTES);
        cudaFuncSetAttribute((const void*)gemm_h<4>, cudaFuncAttributeMaxDynamicSharedMemorySize, SMEM_BYTES);
        cudaFuncSetAttribute((const void*)gemm_h<5>, cudaFuncAttributeMaxDynamicSharedMemorySize, SMEM_BYTES);
        cudaFuncSetAttribute((const void*)gemm_h<6>, cudaFuncAttributeMaxDynamicSharedMemorySize, SMEM_BYTES);
        cudaFuncSetAttribute((const void*)gemm_h<7>, cudaFuncAttributeMaxDynamicSharedMemorySize, SMEM_BYTES);
        attr_done = true;
    }

    // 0. all fp32 -> fp16 conversions in ONE launch
    f2h_all<<<10368, 256>>>(wq, p_wq, wk, p_wk, wv, p_wv, wh, p_wh,
                            key_seq, p_kin, value, p_vin);
    // 1. LayerNorm -> fp16
    ln_kernel<<<M1, 256>>>(query, ln_w, ln_b, p_x);
    // 2. rotary tables -> bias columns of h_q2 / h_k2
    rotab_kernel<<<LL, 64>>>(alpha, beta);
    // 3. base projection: u/r/q (8192 x 2176 x 1024); q lands in h_q2[:, :128]
    gemm_h<0><<<dim3(EE/128, M1/128, 1), 256, SMEM_BYTES>>>(
        p_x, p_wq, DD, DD, DD, 0, 0, nullptr, nullptr, 0, 0, bq, nullptr);
    // 4. k projection (8192 x 128 x 1024) -> h_k2[:, :128]
    gemm_h<2><<<dim3(1, M1/128, 1), 256, SMEM_BYTES>>>(
        p_kin, p_wk, DD, DD, DD, 0, 0, nullptr, p_k2, ZB, 0, bk, nullptr);
    // 5. V projection TRANSPOSED: vT[b][e][c] = silu(wv[e,:]·value[c,b,:] + bv[e])
    gemm_h<5><<<dim3(CCdim/128, DD/128, BB), 256, SMEM_BYTES>>>(
        p_wv, p_vin, DD, DD, BB*DD, 0, (long)DD,
        nullptr, p_vT, CCdim, (long)DD*CCdim, bv, nullptr);
    // 6. QK^T + rotary bias fused as K=256 GEMM -> fp16 scores (into h_p)
    gemm_h<7><<<dim3(CCdim/128, LL/128, BB), 256, SMEM_BYTES>>>(
        p_q2, p_k2, ZB, BB*ZB, BB*ZB, (long)ZB, (long)ZB,
        nullptr, p_p, CCdim, (long)LL*CCdim, nullptr, nullptr);
    // 7. softmax in place on h_p (fp16)
    softmax_kernel<<<BB*LL, 256>>>();
    // 8. attn @ V batched with fused *r -> fp16 h_hx
    gemm_h<6><<<dim3(DD/128, LL/128, BB), 256, SMEM_BYTES>>>(
        p_p, p_vT, CCdim, CCdim, CCdim, (long)LL*CCdim, (long)DD*CCdim,
        nullptr, p_hx, BB*DD, (long)DD, nullptr, p_r);
    // 9. output projection + silu + gated residual (fp32 out)
    gemm_h<4><<<dim3(DD/128, M1/128, 1), 256, SMEM_BYTES>>>(
        p_hx, p_wh, DD, DD, DD, 0, 0, out, nullptr, DD, 0, bh, query);
}